// round 1
// baseline (speedup 1.0000x reference)
#include <cuda_runtime.h>

// SSIM loss: B=64, C=2, H=W=320, WIN=7 (VALID), channel-summing uniform window.
// out = 1 - mean(S), S per output pixel [64,1,314,314].

#define Hh 320
#define Ww 320
#define OH 314
#define OW 314
#define Bb 64
#define CHUNK 40
#define NCHUNK 8
#define NBLOCKS (Bb * NCHUNK)
#define NPIX (64.0 * 314.0 * 314.0)

__device__ float g_partials[NBLOCKS];

__global__ __launch_bounds__(320, 2) void ssim_main(
    const float* __restrict__ X, const float* __restrict__ Y,
    const float* __restrict__ data_range, const float* __restrict__ w) {
    const int t = threadIdx.x;       // input column 0..319
    const int chunk = blockIdx.x;    // 0..7
    const int b = blockIdx.y;        // 0..63
    const int y0 = chunk * CHUNK;
    const int R = min(CHUNK, OH - y0);   // output rows this block

    const float w0 = w[0];                       // uniform weight (1/49)
    const float dr = data_range[b];
    const float C1 = (0.01f * dr) * (0.01f * dr);
    const float C2 = (0.03f * dr) * (0.03f * dr);
    const float cn = 49.0f / 48.0f;              // COV_NORM

    const float* __restrict__ Xb0 = X + (size_t)b * 2 * Hh * Ww;
    const float* __restrict__ Xb1 = Xb0 + Hh * Ww;
    const float* __restrict__ Yb0 = Y + (size_t)b * 2 * Hh * Ww;
    const float* __restrict__ Yb1 = Yb0 + Hh * Ww;

    __shared__ __align__(16) float sm[5][336];
    __shared__ float red[512];

    // zero the pad region of sm once (read by t=78/79 float4 loads)
    if (t < 16) {
#pragma unroll
        for (int s = 0; s < 5; ++s) sm[s][320 + t] = 0.0f;
    }

    // vertical ring buffer of per-row stats (register resident; all indices static)
    float ring[5][7];
    float vsum[5];
#pragma unroll
    for (int s = 0; s < 5; ++s) { vsum[s] = 0.0f; }

    // prologue: input rows y0 .. y0+5
#pragma unroll
    for (int r = 0; r < 6; ++r) {
        const int off = (y0 + r) * Ww + t;
        float x0 = Xb0[off], x1 = Xb1[off];
        float ya = Yb0[off], yb = Yb1[off];
        float s0 = x0 + x1;
        float s1 = ya + yb;
        float s2 = fmaf(x0, x0, x1 * x1);
        float s3 = fmaf(ya, ya, yb * yb);
        float s4 = fmaf(x0, ya, x1 * yb);
        ring[0][r] = s0; vsum[0] += s0;
        ring[1][r] = s1; vsum[1] += s1;
        ring[2][r] = s2; vsum[2] += s2;
        ring[3][r] = s3; vsum[3] += s3;
        ring[4][r] = s4; vsum[4] += s4;
    }
#pragma unroll
    for (int s = 0; s < 5; ++s) ring[s][6] = 0.0f;

    float acc = 0.0f;
    const int c0 = t * 4;            // horizontal-phase columns (threads t<80)

    for (int kk = 0; kk < R; kk += 7) {
#pragma unroll
        for (int u = 0; u < 7; ++u) {
            const int k = kk + u;
            if (k >= R) break;
            // --- load new input row y0+6+k, update vertical sums ---
            {
                const int off = (y0 + 6 + k) * Ww + t;
                float x0 = Xb0[off], x1 = Xb1[off];
                float ya = Yb0[off], yb = Yb1[off];
                float s0 = x0 + x1;
                float s1 = ya + yb;
                float s2 = fmaf(x0, x0, x1 * x1);
                float s3 = fmaf(ya, ya, yb * yb);
                float s4 = fmaf(x0, ya, x1 * yb);
                vsum[0] += s0; vsum[1] += s1; vsum[2] += s2;
                vsum[3] += s3; vsum[4] += s4;
                // new row slot: (6+k)%7 == (6+u)%7 (kk multiple of 7) -> static
                const int sn = (6 + u) % 7;
                ring[0][sn] = s0; ring[1][sn] = s1; ring[2][sn] = s2;
                ring[3][sn] = s3; ring[4][sn] = s4;
            }

            __syncthreads();   // previous iteration's horizontal reads done
#pragma unroll
            for (int s = 0; s < 5; ++s) sm[s][t] = vsum[s];
            __syncthreads();   // column sums visible

            // retire oldest row (row k, slot k%7 == u) for next iteration
            {
                const int so = u;   // k%7 with kk%7==0
#pragma unroll
                for (int s = 0; s < 5; ++s) vsum[s] -= ring[s][so];
            }

            // --- horizontal 7-window sums + SSIM, 4 columns per thread ---
            if (t < 80) {
                float h[5][4];
#pragma unroll
                for (int s = 0; s < 5; ++s) {
                    const float4 va = *(const float4*)&sm[s][c0];
                    const float4 vb = *(const float4*)&sm[s][c0 + 4];
                    const float4 vc = *(const float4*)&sm[s][c0 + 8];
                    float h0 = va.x + va.y + va.z + va.w + vb.x + vb.y + vb.z;
                    float h1 = h0 - va.x + vb.w;
                    float h2 = h1 - va.y + vc.x;
                    float h3 = h2 - va.z + vc.y;
                    h[s][0] = h0; h[s][1] = h1; h[s][2] = h2; h[s][3] = h3;
                }
#pragma unroll
                for (int i = 0; i < 4; ++i) {
                    if (c0 + i < OW) {
                        float ux  = w0 * h[0][i];
                        float uy  = w0 * h[1][i];
                        float uxx = w0 * h[2][i];
                        float uyy = w0 * h[3][i];
                        float uxy = w0 * h[4][i];
                        float vx  = cn * (uxx - ux * ux);
                        float vy  = cn * (uyy - uy * uy);
                        float vxy = cn * (uxy - ux * uy);
                        float A1 = 2.0f * ux * uy + C1;
                        float A2 = 2.0f * vxy + C2;
                        float B1 = ux * ux + uy * uy + C1;
                        float B2 = vx + vy + C2;
                        acc += __fdividef(A1 * A2, B1 * B2);
                    }
                }
            }
        }
    }

    // --- block reduction of acc ---
    __syncthreads();
    red[t] = acc;
    if (t < 192) red[320 + t] = 0.0f;
    __syncthreads();
#pragma unroll
    for (int s = 256; s > 0; s >>= 1) {
        if (t < s) red[t] += red[t + s];
        __syncthreads();
    }
    if (t == 0) g_partials[b * NCHUNK + chunk] = red[0];
}

__global__ void ssim_reduce(float* __restrict__ out) {
    __shared__ double rd[512];
    const int t = threadIdx.x;
    rd[t] = (double)g_partials[t];
    __syncthreads();
#pragma unroll
    for (int s = 256; s > 0; s >>= 1) {
        if (t < s) rd[t] += rd[t + s];
        __syncthreads();
    }
    if (t == 0) out[0] = (float)(1.0 - rd[0] / NPIX);
}

extern "C" void kernel_launch(void* const* d_in, const int* in_sizes, int n_in,
                              void* d_out, int out_size) {
    const float* X  = (const float*)d_in[0];
    const float* Y  = (const float*)d_in[1];
    const float* dr = (const float*)d_in[2];
    const float* w  = (const float*)d_in[3];
    dim3 grid(NCHUNK, Bb);
    ssim_main<<<grid, 320>>>(X, Y, dr, w);
    ssim_reduce<<<1, 512>>>((float*)d_out);
}

// round 2
// speedup vs baseline: 1.9518x; 1.9518x over previous
#include <cuda_runtime.h>

// SSIM loss: B=64, C=2, H=W=320, WIN=7 (VALID), channel-summing uniform window.
// out = 1 - mean(S), S per output pixel [64,1,314,314].

#define Hh 320
#define Ww 320
#define OH 314
#define OW 314
#define Bb 64
#define CHUNK 40
#define NCHUNK 8
#define NBLOCKS (Bb * NCHUNK)
#define NPIX (64.0 * 314.0 * 314.0)
#define GROUP 4

__device__ float g_partials[NBLOCKS];
__device__ unsigned int g_count = 0;

__global__ __launch_bounds__(320, 2) void ssim_main(
    const float* __restrict__ X, const float* __restrict__ Y,
    const float* __restrict__ data_range, const float* __restrict__ w,
    float* __restrict__ out) {
    const int t = threadIdx.x;       // input column 0..319
    const int chunk = blockIdx.x;    // 0..7
    const int b = blockIdx.y;        // 0..63
    const int y0 = chunk * CHUNK;
    const int R = min(CHUNK, OH - y0);           // output rows this block
    const int G = (R + GROUP - 1) / GROUP;       // row groups

    const float w0 = w[0];                       // uniform weight (1/49)
    const float dr = data_range[b];
    const float C1 = (0.01f * dr) * (0.01f * dr);
    const float C2 = (0.03f * dr) * (0.03f * dr);
    const float cn = 49.0f / 48.0f;              // COV_NORM

    const float* __restrict__ Xb0 = X + (size_t)b * 2 * Hh * Ww;
    const float* __restrict__ Xb1 = Xb0 + Hh * Ww;
    const float* __restrict__ Yb0 = Y + (size_t)b * 2 * Hh * Ww;
    const float* __restrict__ Yb1 = Yb0 + Hh * Ww;

    __shared__ __align__(16) float sm[GROUP][5][336];
    __shared__ float red[320];
    __shared__ int s_islast;

    // zero the pad region of sm once (read by tail float4 loads)
    if (t < 16) {
#pragma unroll
        for (int r = 0; r < GROUP; ++r)
#pragma unroll
            for (int s = 0; s < 5; ++s) sm[r][s][320 + t] = 0.0f;
    }

    // 6-slot shift-register ring of per-row stats + running vertical sums
    float ring[5][6];
    float vsum[5];
#pragma unroll
    for (int s = 0; s < 5; ++s) vsum[s] = 0.0f;

    // prologue: input rows y0 .. y0+5
#pragma unroll
    for (int r = 0; r < 6; ++r) {
        const int off = (y0 + r) * Ww + t;
        float x0 = Xb0[off], x1 = Xb1[off];
        float ya = Yb0[off], yb = Yb1[off];
        float s0 = x0 + x1;
        float s1 = ya + yb;
        float s2 = fmaf(x0, x0, x1 * x1);
        float s3 = fmaf(ya, ya, yb * yb);
        float s4 = fmaf(x0, ya, x1 * yb);
        ring[0][r] = s0; vsum[0] += s0;
        ring[1][r] = s1; vsum[1] += s1;
        ring[2][r] = s2; vsum[2] += s2;
        ring[3][r] = s3; vsum[3] += s3;
        ring[4][r] = s4; vsum[4] += s4;
    }

    // prefetch group 0's new input rows (y0+6+k, k=0..3)
    float pf[GROUP][4];
#pragma unroll
    for (int r = 0; r < GROUP; ++r) {
        const int k = r;
        if (k < R) {
            const int off = (y0 + 6 + k) * Ww + t;
            pf[r][0] = Xb0[off]; pf[r][1] = Xb1[off];
            pf[r][2] = Yb0[off]; pf[r][3] = Yb1[off];
        } else {
            pf[r][0] = pf[r][1] = pf[r][2] = pf[r][3] = 0.0f;
        }
    }

    float acc = 0.0f;
    const int hr = t / 80;           // horizontal-phase row within group
    const int hj = t % 80;
    const int c0 = hj * 4;           // horizontal-phase base column

    for (int g = 0; g < G; ++g) {
        // ---- vertical phase: 4 rows of column sums ----
#pragma unroll
        for (int r = 0; r < GROUP; ++r) {
            float x0 = pf[r][0], x1 = pf[r][1];
            float ya = pf[r][2], yb = pf[r][3];
            float s0 = x0 + x1;
            float s1 = ya + yb;
            float s2 = fmaf(x0, x0, x1 * x1);
            float s3 = fmaf(ya, ya, yb * yb);
            float s4 = fmaf(x0, ya, x1 * yb);
            vsum[0] += s0; vsum[1] += s1; vsum[2] += s2;
            vsum[3] += s3; vsum[4] += s4;
            sm[r][0][t] = vsum[0];
            sm[r][1][t] = vsum[1];
            sm[r][2][t] = vsum[2];
            sm[r][3][t] = vsum[3];
            sm[r][4][t] = vsum[4];
            // retire oldest row, shift ring, append new
            vsum[0] -= ring[0][0]; vsum[1] -= ring[1][0]; vsum[2] -= ring[2][0];
            vsum[3] -= ring[3][0]; vsum[4] -= ring[4][0];
#pragma unroll
            for (int s = 0; s < 5; ++s) {
#pragma unroll
                for (int i = 0; i < 5; ++i) ring[s][i] = ring[s][i + 1];
            }
            ring[0][5] = s0; ring[1][5] = s1; ring[2][5] = s2;
            ring[3][5] = s3; ring[4][5] = s4;
        }

        __syncthreads();   // column sums visible

        // ---- prefetch next group's input rows (hides DRAM under horizontal) ----
#pragma unroll
        for (int r = 0; r < GROUP; ++r) {
            const int k = GROUP * (g + 1) + r;
            if (k < R) {
                const int off = (y0 + 6 + k) * Ww + t;
                pf[r][0] = Xb0[off]; pf[r][1] = Xb1[off];
                pf[r][2] = Yb0[off]; pf[r][3] = Yb1[off];
            } else {
                pf[r][0] = pf[r][1] = pf[r][2] = pf[r][3] = 0.0f;
            }
        }

        // ---- horizontal phase: all 320 threads (4 rows x 80 col-groups) ----
        {
            const int k = GROUP * g + hr;
            if (k < R) {
                float h[5][4];
#pragma unroll
                for (int s = 0; s < 5; ++s) {
                    const float4 va = *(const float4*)&sm[hr][s][c0];
                    const float4 vb = *(const float4*)&sm[hr][s][c0 + 4];
                    const float4 vc = *(const float4*)&sm[hr][s][c0 + 8];
                    float h0 = va.x + va.y + va.z + va.w + vb.x + vb.y + vb.z;
                    float h1 = h0 - va.x + vb.w;
                    float h2 = h1 - va.y + vc.x;
                    float h3 = h2 - va.z + vc.y;
                    h[s][0] = h0; h[s][1] = h1; h[s][2] = h2; h[s][3] = h3;
                }
#pragma unroll
                for (int i = 0; i < 4; ++i) {
                    if (c0 + i < OW) {
                        float ux  = w0 * h[0][i];
                        float uy  = w0 * h[1][i];
                        float uxx = w0 * h[2][i];
                        float uyy = w0 * h[3][i];
                        float uxy = w0 * h[4][i];
                        float vx  = cn * (uxx - ux * ux);
                        float vy  = cn * (uyy - uy * uy);
                        float vxy = cn * (uxy - ux * uy);
                        float A1 = 2.0f * ux * uy + C1;
                        float A2 = 2.0f * vxy + C2;
                        float B1 = ux * ux + uy * uy + C1;
                        float B2 = vx + vy + C2;
                        acc += __fdividef(A1 * A2, B1 * B2);
                    }
                }
            }
        }

        __syncthreads();   // horizontal reads done before next vertical writes
    }

    // ---- block reduction of acc (fixed order -> deterministic) ----
    red[t] = acc;
    __syncthreads();
    if (t < 160) red[t] += red[t + 160];
    __syncthreads();
    if (t < 80) red[t] += red[t + 80];
    __syncthreads();
    if (t < 40) red[t] += red[t + 40];
    __syncthreads();
    if (t < 20) red[t] += red[t + 20];
    __syncthreads();
    if (t < 10) red[t] += red[t + 10];
    __syncthreads();
    if (t < 5) red[t] += red[t + 5];
    __syncthreads();

    if (t == 0) {
        float v = red[0] + red[1] + red[2] + red[3] + red[4];
        g_partials[b * NCHUNK + chunk] = v;
        __threadfence();
        unsigned int old = atomicAdd(&g_count, 1u);
        s_islast = (old == NBLOCKS - 1);
    }
    __syncthreads();

    // ---- last block finishes the global reduction (deterministic order) ----
    if (s_islast) {
        __threadfence();
        float v = g_partials[t];
        if (t < NBLOCKS - 320) v += g_partials[t + 320];
        red[t] = v;
        __syncthreads();
        if (t < 160) red[t] += red[t + 160];
        __syncthreads();
        if (t < 80) red[t] += red[t + 80];
        __syncthreads();
        if (t < 40) red[t] += red[t + 40];
        __syncthreads();
        if (t < 20) red[t] += red[t + 20];
        __syncthreads();
        if (t < 10) red[t] += red[t + 10];
        __syncthreads();
        if (t < 5) red[t] += red[t + 5];
        __syncthreads();
        if (t == 0) {
            double total = (double)(red[0] + red[1] + red[2] + red[3] + red[4]);
            out[0] = (float)(1.0 - total / NPIX);
            g_count = 0;   // reset for next graph replay
        }
    }
}

extern "C" void kernel_launch(void* const* d_in, const int* in_sizes, int n_in,
                              void* d_out, int out_size) {
    const float* X  = (const float*)d_in[0];
    const float* Y  = (const float*)d_in[1];
    const float* dr = (const float*)d_in[2];
    const float* w  = (const float*)d_in[3];
    dim3 grid(NCHUNK, Bb);
    ssim_main<<<grid, 320>>>(X, Y, dr, w, (float*)d_out);
}